// round 8
// baseline (speedup 1.0000x reference)
#include <cuda_runtime.h>
#include <cstdint>

// Shapes (fixed):
//   x_main: [1, T=128, M=512, K=256] fp32
//   x_aux : [K=256, T=128, Da=256]   fp32
//   W     : [Da=256, E=512]          fp32
//   b     : [E=512]                  fp32
//   out   : [1,T,M,E,1] = [128,512,512] fp32
//
// R4 structure (best known) with FATTER warps: warp tile 64x64, 4 warps/CTA
// (128 threads), CTA tile 128x128.  Halves smem read amplification
// (A amp 4x->2x) and total issue vs R4 while keeping all verified
// conflict-free layouts and the round-once tf32 numerics.
//
// Stage 1 (per t): scratch[t][e][k] = relu( sum_d W[d][e]*x_aux[k][t][d] + b[e] )
//   M=e(512), N=k(256), red=d.  A = W (pre-rounded tf32, natural [d][e] smem,
//   transposed at fragment gather), B = x_aux rows (LDG+cvt+STS).
// Stage 2 (per t): out[t][m][e] = sum_k x_main[t][m][k] * scratch[t][e][k]
//   M=m(512), N=e(512), red=k.  A = x_main (LDG+cvt+STS), B = scratch
//   (tf32-rounded by stage-1 epilogue, cp.async).

__device__ __align__(16) float g_scratch[128 * 512 * 256];  // [T][E][K], 64 MB
__device__ __align__(16) float g_Wtf32[256 * 512];          // W pre-rounded

static constexpr int S_A = 18432;   // 128*36*4 (>= 32*136*4 = 17408 W tile)
static constexpr int S_B = 18432;   // 128*36*4
static constexpr int SMEM_TOTAL = 2 * (S_A + S_B);   // 73728 -> 2 CTAs/SM

__device__ __forceinline__ uint32_t smem_u32(const void* p) {
    uint32_t a;
    asm("{ .reg .u64 t; cvta.to.shared.u64 t, %1; cvt.u32.u64 %0, t; }" : "=r"(a) : "l"(p));
    return a;
}
__device__ __forceinline__ float f2tf32f(float f) {
    uint32_t r;
    asm("cvt.rna.tf32.f32 %0, %1;" : "=r"(r) : "f"(f));
    return __uint_as_float(r);
}
#define CP_ASYNC16(dst32, src) \
    asm volatile("cp.async.cg.shared.global [%0], [%1], 16;" :: "r"(dst32), "l"(src))
#define CP_COMMIT() asm volatile("cp.async.commit_group;" ::: "memory")
#define CP_WAIT0()  asm volatile("cp.async.wait_group 0;" ::: "memory")
#define STS128(addr, v) \
    asm volatile("st.shared.v4.b32 [%0], {%1,%2,%3,%4};" \
                 :: "r"(addr), "f"(v.x), "f"(v.y), "f"(v.z), "f"(v.w) : "memory")

__device__ __forceinline__ void mma_tf32(float* d, uint32_t a0, uint32_t a1,
                                         uint32_t a2, uint32_t a3,
                                         uint32_t b0, uint32_t b1) {
    asm volatile(
        "mma.sync.aligned.m16n8k8.row.col.f32.tf32.tf32.f32 "
        "{%0,%1,%2,%3}, {%4,%5,%6,%7}, {%8,%9}, {%0,%1,%2,%3};"
        : "+f"(d[0]), "+f"(d[1]), "+f"(d[2]), "+f"(d[3])
        : "r"(a0), "r"(a1), "r"(a2), "r"(a3), "r"(b0), "r"(b1));
}

// Pre-pass: round W to tf32 once (natural [d][e] layout)
__global__ void w_round_kernel(const float* __restrict__ W) {
    const int i = blockIdx.x * 256 + threadIdx.x;   // 32768 float4
    float4 v = reinterpret_cast<const float4*>(W)[i];
    v.x = f2tf32f(v.x); v.y = f2tf32f(v.y); v.z = f2tf32f(v.z); v.w = f2tf32f(v.w);
    reinterpret_cast<float4*>(g_Wtf32)[i] = v;
}

// CTA: 128x128, 4 warps in 2(m) x 2(n), warp tile 64x64.
template <bool STAGE1>
__global__ void __launch_bounds__(128, 2)
slam_mma_kernel(const float* __restrict__ Aglob, const float* __restrict__ Bglob,
                const float* __restrict__ bias, float* __restrict__ Cglob) {
    extern __shared__ __align__(16) char smem[];
    const uint32_t sb = smem_u32(smem);
    const int tid = threadIdx.x, wid = tid >> 5, lid = tid & 31;
    const int g = lid >> 2, tg = lid & 3;
    const int warp_m = (wid & 1) * 64;
    const int warp_n = (wid >> 1) * 64;
    const int t = blockIdx.z, m0 = blockIdx.y * 128, n0 = blockIdx.x * 128;

    // cp.async operand: stage1 -> A (W, pre-rounded); stage2 -> B (scratch, pre-rounded)
    // LDG-staged operand: stage1 -> B (x_aux);        stage2 -> A (x_main)
    const float* ld_src;  size_t ld_rstride;
    const float* cp_src = nullptr;
    float* C;
    if (STAGE1) {
        ld_src = Bglob + (size_t)t * 256;            // x_aux[.,t,.], rows k
        ld_rstride = 128 * 256;
        C = g_scratch + (size_t)t * 512 * 256;       // [e][k]
    } else {
        ld_src = Aglob + (size_t)t * 512 * 256;      // x_main[t], rows m
        ld_rstride = 256;
        cp_src = g_scratch + (size_t)t * 512 * 256;  // rows e
        C = Cglob + (size_t)t * 512 * 512;
    }

    const uint32_t aoff[2] = {sb, sb + S_A};
    const uint32_t boff[2] = {sb + 2 * S_A, sb + 2 * S_A + S_B};

    // ---- cp.async tile ----
    auto cpasync_tile = [&](int kt, int buf) {
        if (STAGE1) {
            // W tile [32 d][128 e], ld=136 floats (544 B rows); 1024 float4
#pragma unroll
            for (int i = 0; i < 8; ++i) {
                const int idx = tid + i * 128;
                const int row = idx >> 5, ch = idx & 31;
                CP_ASYNC16(aoff[buf] + row * 544 + ch * 16,
                           g_Wtf32 + (size_t)(kt * 32 + row) * 512 + m0 + ch * 4);
            }
        } else {
            // scratch tile [128 e][32 k], ld=36 floats (144 B rows); 1024 float4
#pragma unroll
            for (int i = 0; i < 8; ++i) {
                const int idx = tid + i * 128;
                const int row = idx >> 3, ch = idx & 7;
                CP_ASYNC16(boff[buf] + row * 144 + ch * 16,
                           cp_src + (size_t)(n0 + row) * 256 + kt * 32 + ch * 4);
            }
        }
    };

    // ---- register-staged LDG of the other operand: tile [128 rows][32], 8 float4/thread ----
    const int srow = tid >> 3, sch = tid & 7;   // srow 0..15
    auto ldg_tile = [&](int kt, float4 (&r)[8]) {
        const int base_row = STAGE1 ? n0 : m0;
#pragma unroll
        for (int i = 0; i < 8; ++i)
            r[i] = *reinterpret_cast<const float4*>(
                ld_src + (size_t)(base_row + srow + i * 16) * ld_rstride
                       + kt * 32 + sch * 4);
    };
    auto sts_tile = [&](float4 (&r)[8], int buf) {
        const uint32_t base = (STAGE1 ? boff[buf] : aoff[buf]) + srow * 144 + sch * 16;
#pragma unroll
        for (int i = 0; i < 8; ++i) {
            float4 v = r[i];
            v.x = f2tf32f(v.x); v.y = f2tf32f(v.y);
            v.z = f2tf32f(v.z); v.w = f2tf32f(v.w);
            STS128(base + i * 16 * 144, v);
        }
    };

    float acc[4][8][4];
#pragma unroll
    for (int mi = 0; mi < 4; ++mi)
#pragma unroll
        for (int nj = 0; nj < 8; ++nj)
#pragma unroll
            for (int q = 0; q < 4; ++q) acc[mi][nj][q] = 0.0f;

    auto compute_tile = [&](int buf) {
        const float* As = (const float*)(smem + (buf ? S_A : 0));
        const float* Bs = (const float*)(smem + 2 * S_A + (buf ? S_B : 0));
#pragma unroll
        for (int ks = 0; ks < 4; ++ks) {
            const int k8 = ks * 8;
            uint32_t af[4][4], bf[8][2];
#pragma unroll
            for (int mi = 0; mi < 4; ++mi) {
                if (STAGE1) {
                    const int e_ = warp_m + 16 * mi + g;
                    const int d_ = k8 + tg;
                    af[mi][0] = __float_as_uint(As[d_ * 136 + e_]);
                    af[mi][1] = __float_as_uint(As[d_ * 136 + e_ + 8]);
                    af[mi][2] = __float_as_uint(As[(d_ + 4) * 136 + e_]);
                    af[mi][3] = __float_as_uint(As[(d_ + 4) * 136 + e_ + 8]);
                } else {
                    const int r_ = warp_m + 16 * mi + g;
                    const int c_ = k8 + tg;
                    af[mi][0] = __float_as_uint(As[r_ * 36 + c_]);
                    af[mi][1] = __float_as_uint(As[(r_ + 8) * 36 + c_]);
                    af[mi][2] = __float_as_uint(As[r_ * 36 + c_ + 4]);
                    af[mi][3] = __float_as_uint(As[(r_ + 8) * 36 + c_ + 4]);
                }
            }
#pragma unroll
            for (int nj = 0; nj < 8; ++nj) {
                const int n_ = warp_n + 8 * nj + g;
                bf[nj][0] = __float_as_uint(Bs[n_ * 36 + k8 + tg]);
                bf[nj][1] = __float_as_uint(Bs[n_ * 36 + k8 + tg + 4]);
            }
#pragma unroll
            for (int mi = 0; mi < 4; ++mi)
#pragma unroll
                for (int nj = 0; nj < 8; ++nj)
                    mma_tf32(acc[mi][nj], af[mi][0], af[mi][1], af[mi][2], af[mi][3],
                             bf[nj][0], bf[nj][1]);
        }
    };

    // ---- pipelined mainloop: 8 k-tiles of 32, double-buffered ----
    float4 stage_regs[8];
    cpasync_tile(0, 0);
    CP_COMMIT();
    ldg_tile(0, stage_regs);
    CP_WAIT0();
    sts_tile(stage_regs, 0);
    __syncthreads();

    int buf = 0;
#pragma unroll 1
    for (int kt = 0; kt < 8; ++kt) {
        if (kt < 7) {
            cpasync_tile(kt + 1, buf ^ 1);
            CP_COMMIT();
            ldg_tile(kt + 1, stage_regs);
        }
        compute_tile(buf);
        if (kt < 7) {
            CP_WAIT0();
            sts_tile(stage_regs, buf ^ 1);
            __syncthreads();
        }
        buf ^= 1;
    }

    // ---- epilogue ----
    const int cld = STAGE1 ? 256 : 512;
#pragma unroll
    for (int mi = 0; mi < 4; ++mi) {
        const int r0 = m0 + warp_m + 16 * mi + g;
        const int r1 = r0 + 8;
        float bv0 = 0.0f, bv1 = 0.0f;
        if (STAGE1) { bv0 = bias[r0]; bv1 = bias[r1]; }
#pragma unroll
        for (int nj = 0; nj < 8; ++nj) {
            const int col = n0 + warp_n + 8 * nj + 2 * tg;
            float2 v0, v1;
            v0.x = acc[mi][nj][0]; v0.y = acc[mi][nj][1];
            v1.x = acc[mi][nj][2]; v1.y = acc[mi][nj][3];
            if (STAGE1) {
                v0.x = f2tf32f(fmaxf(v0.x + bv0, 0.0f));
                v0.y = f2tf32f(fmaxf(v0.y + bv0, 0.0f));
                v1.x = f2tf32f(fmaxf(v1.x + bv1, 0.0f));
                v1.y = f2tf32f(fmaxf(v1.y + bv1, 0.0f));
            }
            *reinterpret_cast<float2*>(C + (size_t)r0 * cld + col) = v0;
            *reinterpret_cast<float2*>(C + (size_t)r1 * cld + col) = v1;
        }
    }
}

extern "C" void kernel_launch(void* const* d_in, const int* in_sizes, int n_in,
                              void* d_out, int out_size) {
    const float* x_main = (const float*)d_in[0];  // [1,128,512,256]
    const float* x_aux  = (const float*)d_in[1];  // [256,128,256]
    const float* W      = (const float*)d_in[2];  // [256,512]
    const float* b      = (const float*)d_in[3];  // [512]
    float* out = (float*)d_out;                   // [128,512,512]

    cudaFuncSetAttribute(slam_mma_kernel<true>,
                         cudaFuncAttributeMaxDynamicSharedMemorySize, SMEM_TOTAL);
    cudaFuncSetAttribute(slam_mma_kernel<false>,
                         cudaFuncAttributeMaxDynamicSharedMemorySize, SMEM_TOTAL);

    // W -> tf32 (once per launch)
    w_round_kernel<<<128, 256>>>(W);
    // Stage 1: per-t  D[e(512) x k(256)] = W^T x_aux[.,t,.]^T (+bias, relu) -> scratch
    slam_mma_kernel<true><<<dim3(2, 4, 128), 128, SMEM_TOTAL>>>(nullptr, x_aux, b, nullptr);
    // Stage 2: per-t  D[m(512) x e(512)] = x_main[t] . scratch[t]^T -> out
    slam_mma_kernel<false><<<dim3(4, 4, 128), 128, SMEM_TOTAL>>>(x_main, nullptr, nullptr, out);
}

// round 9
// speedup vs baseline: 1.5465x; 1.5465x over previous
#include <cuda_runtime.h>
#include <cstdint>

// Shapes (fixed):
//   x_main: [1, T=128, M=512, K=256] fp32
//   x_aux : [K=256, T=128, Da=256]   fp32
//   W     : [Da=256, E=512]          fp32
//   b     : [E=512]                  fp32
//   out   : [1,T,M,E,1] = [128,512,512] fp32
//
// R4 pipeline (best known: 186.6us) with all fragment loads converted to
// ldmatrix.x4 (tf32-as-2xb16 trick): 96 scalar LDS -> 24 LDSM per thread per
// k-tile.  Pre-pass transposes W to Wt[e][d] (tf32-rounded) so BOTH stages
// share one k-major mainloop:
//   Stage 1 (per t): scratch[t][e][k] = relu( sum_d Wt[e][d]*x_aux[k][t][d] + b[e] )
//     A = Wt rows e (cp.async), B = x_aux rows k (LDG+cvt+STS).
//   Stage 2 (per t): out[t][m][e] = sum_k x_main[t][m][k]*scratch[t][e][k]
//     A = x_main rows m (LDG+cvt+STS), B = scratch rows e (cp.async, pre-rounded).
// All values rna-rounded to tf32 exactly once (numerics identical to R3/R4).

__device__ __align__(16) float g_scratch[128 * 512 * 256];  // [T][E][K], 64 MB
__device__ __align__(16) float g_Wt[512 * 256];             // W^T, tf32-rounded

static constexpr int S_A = 18432;   // 128 rows x 36 floats (144 B rows)
static constexpr int S_B = 18432;
static constexpr int SMEM_TOTAL = 2 * (S_A + S_B);   // 73728 -> 2 CTAs/SM

__device__ __forceinline__ uint32_t smem_u32(const void* p) {
    uint32_t a;
    asm("{ .reg .u64 t; cvta.to.shared.u64 t, %1; cvt.u32.u64 %0, t; }" : "=r"(a) : "l"(p));
    return a;
}
__device__ __forceinline__ float f2tf32f(float f) {
    uint32_t r;
    asm("cvt.rna.tf32.f32 %0, %1;" : "=r"(r) : "f"(f));
    return __uint_as_float(r);
}
#define CP_ASYNC16(dst32, src) \
    asm volatile("cp.async.cg.shared.global [%0], [%1], 16;" :: "r"(dst32), "l"(src))
#define CP_COMMIT() asm volatile("cp.async.commit_group;" ::: "memory")
#define CP_WAIT0()  asm volatile("cp.async.wait_group 0;" ::: "memory")
#define STS128(addr, v) \
    asm volatile("st.shared.v4.b32 [%0], {%1,%2,%3,%4};" \
                 :: "r"(addr), "f"(v.x), "f"(v.y), "f"(v.z), "f"(v.w) : "memory")
#define LDSM4(r0, r1, r2, r3, addr) \
    asm volatile("ldmatrix.sync.aligned.m8n8.x4.shared.b16 {%0,%1,%2,%3}, [%4];" \
                 : "=r"(r0), "=r"(r1), "=r"(r2), "=r"(r3) : "r"(addr))

__device__ __forceinline__ void mma_tf32(float* d, uint32_t a0, uint32_t a1,
                                         uint32_t a2, uint32_t a3,
                                         uint32_t b0, uint32_t b1) {
    asm volatile(
        "mma.sync.aligned.m16n8k8.row.col.f32.tf32.tf32.f32 "
        "{%0,%1,%2,%3}, {%4,%5,%6,%7}, {%8,%9}, {%0,%1,%2,%3};"
        : "+f"(d[0]), "+f"(d[1]), "+f"(d[2]), "+f"(d[3])
        : "r"(a0), "r"(a1), "r"(a2), "r"(a3), "r"(b0), "r"(b1));
}

// Pre-pass: Wt[e][d] = rna_tf32(W[d][e]).  32x32 smem-tiled transpose.
__global__ void w_transpose_kernel(const float* __restrict__ W) {
    __shared__ float s[32][33];
    const int d0 = blockIdx.x * 32, e0 = blockIdx.y * 32;
    const int tx = threadIdx.x, ty = threadIdx.y;
    s[ty][tx] = W[(size_t)(d0 + ty) * 512 + e0 + tx];
    __syncthreads();
    g_Wt[(size_t)(e0 + ty) * 256 + d0 + tx] = f2tf32f(s[tx][ty]);
}

// CTA 128x128, 8 warps (2m x 4n), warp tile 64x32 — R4's exact shape.
template <bool STAGE1>
__global__ void __launch_bounds__(256, 2)
slam_mma_kernel(const float* __restrict__ Aglob, const float* __restrict__ Bglob,
                const float* __restrict__ bias, float* __restrict__ Cglob) {
    extern __shared__ __align__(16) char smem[];
    const uint32_t sb = smem_u32(smem);
    const int tid = threadIdx.x, wid = tid >> 5, lid = tid & 31;
    const int g = lid >> 2, tg = lid & 3;
    const int warp_m = (wid & 1) * 64;
    const int warp_n = (wid >> 1) * 32;
    const int t = blockIdx.z, m0 = blockIdx.y * 128, n0 = blockIdx.x * 128;

    // cp.async operand (pre-rounded tf32, k-major rows):
    //   stage1 -> A = Wt rows e;  stage2 -> B = scratch rows e
    // LDG-staged operand: stage1 -> B = x_aux rows k; stage2 -> A = x_main rows m
    const float* cp_src;  size_t cp_rstride;
    const float* ld_src;  size_t ld_rstride;
    float* C;
    if (STAGE1) {
        cp_src = g_Wt;   cp_rstride = 256;            // rows e (use m0)
        ld_src = Bglob + (size_t)t * 256;             // x_aux[.,t,.], rows k (use n0)
        ld_rstride = 128 * 256;
        C = g_scratch + (size_t)t * 512 * 256;        // [e][k]
    } else {
        ld_src = Aglob + (size_t)t * 512 * 256;       // x_main[t], rows m (use m0)
        ld_rstride = 256;
        cp_src = g_scratch + (size_t)t * 512 * 256;   // rows e (use n0)
        cp_rstride = 256;
        C = Cglob + (size_t)t * 512 * 512;
    }

    const uint32_t aoff[2] = {sb, sb + S_A};
    const uint32_t boff[2] = {sb + 2 * S_A, sb + 2 * S_A + S_B};

    // ---- cp.async tile: [128 rows][32 k], ld=36 floats (144 B rows) ----
    auto cpasync_tile = [&](int kt, int buf) {
        const int base_row = STAGE1 ? m0 : n0;
        const uint32_t dst = STAGE1 ? aoff[buf] : boff[buf];
#pragma unroll
        for (int i = 0; i < 4; ++i) {
            const int idx = tid + i * 256;            // 0..1023
            const int row = idx >> 3, ch = idx & 7;
            CP_ASYNC16(dst + row * 144 + ch * 16,
                       cp_src + (size_t)(base_row + row) * cp_rstride + kt * 32 + ch * 4);
        }
    };

    // ---- register-staged LDG of the other operand: [128 rows][32], 4 float4 ----
    const int srow = tid >> 3, sch = tid & 7;         // srow 0..31
    auto ldg_tile = [&](int kt, float4 (&r)[4]) {
        const int base_row = STAGE1 ? n0 : m0;
#pragma unroll
        for (int i = 0; i < 4; ++i)
            r[i] = *reinterpret_cast<const float4*>(
                ld_src + (size_t)(base_row + srow + i * 32) * ld_rstride
                       + kt * 32 + sch * 4);
    };
    auto sts_tile = [&](float4 (&r)[4], int buf) {
        const uint32_t base = (STAGE1 ? boff[buf] : aoff[buf]) + srow * 144 + sch * 16;
#pragma unroll
        for (int i = 0; i < 4; ++i) {
            float4 v = r[i];
            v.x = f2tf32f(v.x); v.y = f2tf32f(v.y);
            v.z = f2tf32f(v.z); v.w = f2tf32f(v.w);
            STS128(base + i * 32 * 144, v);
        }
    };

    // ---- LDSM lane offsets (bytes) ----
    // A frag (16x8): matrices {rows0-7 k0-3, rows8-15 k0-3, rows0-7 k4-7, rows8-15 k4-7}
    const uint32_t a_lane = (uint32_t)(((((lid >> 3) & 1) * 8) + (lid & 7)) * 144
                                       + ((lid >> 4) & 1) * 16);
    // B pair (16 n-rows x 8k): matrices {n0-7 k0-3, n0-7 k4-7, n8-15 k0-3, n8-15 k4-7}
    const uint32_t b_lane = (uint32_t)(((((lid >> 4) & 1) * 8) + (lid & 7)) * 144
                                       + ((lid >> 3) & 1) * 16);

    float acc[4][4][4];
#pragma unroll
    for (int mi = 0; mi < 4; ++mi)
#pragma unroll
        for (int nj = 0; nj < 4; ++nj)
#pragma unroll
            for (int q = 0; q < 4; ++q) acc[mi][nj][q] = 0.0f;

    auto compute_tile = [&](int buf) {
        const uint32_t ab = aoff[buf] + a_lane + warp_m * 144;
        const uint32_t bb = boff[buf] + b_lane + warp_n * 144;
#pragma unroll
        for (int ks = 0; ks < 4; ++ks) {
            uint32_t af[4][4], bf[4][2];
#pragma unroll
            for (int mi = 0; mi < 4; ++mi)
                LDSM4(af[mi][0], af[mi][1], af[mi][2], af[mi][3],
                      ab + mi * (16 * 144) + ks * 32);
#pragma unroll
            for (int p = 0; p < 2; ++p)
                LDSM4(bf[2 * p][0], bf[2 * p][1], bf[2 * p + 1][0], bf[2 * p + 1][1],
                      bb + p * (16 * 144) + ks * 32);
#pragma unroll
            for (int mi = 0; mi < 4; ++mi)
#pragma unroll
                for (int nj = 0; nj < 4; ++nj)
                    mma_tf32(acc[mi][nj], af[mi][0], af[mi][1], af[mi][2], af[mi][3],
                             bf[nj][0], bf[nj][1]);
        }
    };

    // ---- pipelined mainloop: 8 k-tiles of 32, double-buffered ----
    float4 stage_regs[4];
    cpasync_tile(0, 0);
    CP_COMMIT();
    ldg_tile(0, stage_regs);
    CP_WAIT0();
    sts_tile(stage_regs, 0);
    __syncthreads();

    int buf = 0;
#pragma unroll 1
    for (int kt = 0; kt < 8; ++kt) {
        if (kt < 7) {
            cpasync_tile(kt + 1, buf ^ 1);
            CP_COMMIT();
            ldg_tile(kt + 1, stage_regs);
        }
        compute_tile(buf);
        if (kt < 7) {
            CP_WAIT0();
            sts_tile(stage_regs, buf ^ 1);
            __syncthreads();
        }
        buf ^= 1;
    }

    // ---- epilogue (R4's, verified) ----
    const int cld = STAGE1 ? 256 : 512;
#pragma unroll
    for (int mi = 0; mi < 4; ++mi) {
        const int r0 = m0 + warp_m + 16 * mi + g;
        const int r1 = r0 + 8;
        float bv0 = 0.0f, bv1 = 0.0f;
        if (STAGE1) { bv0 = bias[r0]; bv1 = bias[r1]; }
#pragma unroll
        for (int nj = 0; nj < 4; ++nj) {
            const int col = n0 + warp_n + 8 * nj + 2 * tg;
            float2 v0, v1;
            v0.x = acc[mi][nj][0]; v0.y = acc[mi][nj][1];
            v1.x = acc[mi][nj][2]; v1.y = acc[mi][nj][3];
            if (STAGE1) {
                v0.x = f2tf32f(fmaxf(v0.x + bv0, 0.0f));
                v0.y = f2tf32f(fmaxf(v0.y + bv0, 0.0f));
                v1.x = f2tf32f(fmaxf(v1.x + bv1, 0.0f));
                v1.y = f2tf32f(fmaxf(v1.y + bv1, 0.0f));
            }
            *reinterpret_cast<float2*>(C + (size_t)r0 * cld + col) = v0;
            *reinterpret_cast<float2*>(C + (size_t)r1 * cld + col) = v1;
        }
    }
}

extern "C" void kernel_launch(void* const* d_in, const int* in_sizes, int n_in,
                              void* d_out, int out_size) {
    const float* x_main = (const float*)d_in[0];  // [1,128,512,256]
    const float* x_aux  = (const float*)d_in[1];  // [256,128,256]
    const float* W      = (const float*)d_in[2];  // [256,512]
    const float* b      = (const float*)d_in[3];  // [512]
    float* out = (float*)d_out;                   // [128,512,512]

    cudaFuncSetAttribute(slam_mma_kernel<true>,
                         cudaFuncAttributeMaxDynamicSharedMemorySize, SMEM_TOTAL);
    cudaFuncSetAttribute(slam_mma_kernel<false>,
                         cudaFuncAttributeMaxDynamicSharedMemorySize, SMEM_TOTAL);

    // W -> Wt (tf32-rounded transpose), once per launch
    w_transpose_kernel<<<dim3(8, 16), dim3(32, 32)>>>(W);
    // Stage 1: per-t  D[e(512) x k(256)] = Wt . x_aux[.,t,.]^T (+bias, relu) -> scratch
    slam_mma_kernel<true><<<dim3(2, 4, 128), 256, SMEM_TOTAL>>>(nullptr, x_aux, b, nullptr);
    // Stage 2: per-t  D[m(512) x e(512)] = x_main[t] . scratch[t]^T -> out
    slam_mma_kernel<false><<<dim3(4, 4, 128), 256, SMEM_TOTAL>>>(x_main, nullptr, nullptr, out);
}